// round 2
// baseline (speedup 1.0000x reference)
#include <cuda_runtime.h>
#include <cstdint>

#define D     256
#define K     2048
#define BHW   4096      // H*W per batch
#define NPIX  65536     // 16 * 64 * 64
#define QELEMS 16777216 // 16*256*64*64

// Scratch (device globals: no allocations allowed)
__device__ float g_halfnorm[K];
__device__ int   g_idx[NPIX];
__device__ int   g_counts[K];
__device__ float g_loss;

// ---- packed f32x2 helpers (sm_100+ PTX) ----
__device__ __forceinline__ unsigned long long pack2(float lo, float hi) {
    unsigned long long r;
    asm("mov.b64 %0, {%1, %2};" : "=l"(r) : "f"(lo), "f"(hi));
    return r;
}
__device__ __forceinline__ void unpack2(unsigned long long v, float& lo, float& hi) {
    asm("mov.b64 {%0, %1}, %2;" : "=f"(lo), "=f"(hi) : "l"(v));
}
__device__ __forceinline__ unsigned long long fma2(unsigned long long a,
                                                   unsigned long long b,
                                                   unsigned long long c) {
    unsigned long long r;
    asm("fma.rn.f32x2 %0, %1, %2, %3;" : "=l"(r) : "l"(a), "l"(b), "l"(c));
    return r;
}

// ---- kernel 1: 0.5*||e_k||^2, zero counts & loss accumulator ----
__global__ void prep_kernel(const float* __restrict__ emb) {
    int k = blockIdx.x * blockDim.x + threadIdx.x;
    if (k < K) {
        const float4* row = reinterpret_cast<const float4*>(emb + (size_t)k * D);
        float s = 0.f;
        #pragma unroll
        for (int i = 0; i < D / 4; i++) {
            float4 v = row[i];
            s += v.x * v.x + v.y * v.y + v.z * v.z + v.w * v.w;
        }
        g_halfnorm[k] = 0.5f * s;
        g_counts[k] = 0;
        if (k == 0) g_loss = 0.f;
    }
}

// ---- kernel 2: fused GEMM + argmin ----
// score(n,k) = 0.5||e_k||^2 - x_n . e_k   (same argmin as squared distance)
#define PT 128   // pixels per block
#define KT 128   // k per chunk
#define DT 32    // d per smem tile
#define ESTRIDE 132  // padded k-stride for e tile (bank-conflict mitigation)

__global__ __launch_bounds__(256, 2) void argmin_kernel(
    const float* __restrict__ x, const float* __restrict__ emb) {
    __shared__ float xs[DT * PT];       // negated x, [d][px]
    __shared__ float es[DT * ESTRIDE];  // e, [d][k] padded

    int tid = threadIdx.x;
    int tx = tid & 15;          // k dimension (8 k each)
    int ty = tid >> 4;          // px dimension (8 px each)
    int blk = blockIdx.x;       // 512 blocks
    int b   = blk >> 5;         // 32 pixel-tiles per batch image
    int hw0 = (blk & 31) * PT;
    const float* xg = x + (size_t)b * (D * BHW) + hw0;  // xg[d*BHW + p]

    float best[8];
    int   besti[8];
    #pragma unroll
    for (int i = 0; i < 8; i++) { best[i] = 3.4e38f; besti[i] = 0; }

    for (int kc = 0; kc < K; kc += KT) {
        int kbase = kc + tx * 8;
        unsigned long long acc[8][4];
        {
            const float2* hn2 = reinterpret_cast<const float2*>(&g_halfnorm[kbase]);
            #pragma unroll
            for (int j = 0; j < 4; j++) {
                float2 h = hn2[j];
                unsigned long long hp = pack2(h.x, h.y);
                #pragma unroll
                for (int i = 0; i < 8; i++) acc[i][j] = hp;
            }
        }
        for (int dt = 0; dt < D; dt += DT) {
            __syncthreads();
            // load x tile (negated): DT*PT floats, float4, fully coalesced
            #pragma unroll
            for (int u = 0; u < 4; u++) {
                int f4 = tid + u * 256;        // 0..1023
                int dd = f4 >> 5;              // 0..31
                int pp = (f4 & 31) << 2;       // 0..124
                float4 v = *reinterpret_cast<const float4*>(
                    xg + (size_t)(dt + dd) * BHW + pp);
                *reinterpret_cast<float4*>(&xs[dd * PT + pp]) =
                    make_float4(-v.x, -v.y, -v.z, -v.w);
            }
            // load e tile transposed to [d][k]: 4 coalesced scalar LDG + 1 STS.128
            #pragma unroll
            for (int u = 0; u < 4; u++) {
                int idx = tid + u * 256;       // 0..1023
                int dp = idx & 31;             // d within tile
                int kg = idx >> 5;             // k group of 4
                const float* ep = emb + (size_t)(kc + kg * 4) * D + dt + dp;
                float4 v = make_float4(ep[0], ep[D], ep[2 * D], ep[3 * D]);
                *reinterpret_cast<float4*>(&es[dp * ESTRIDE + kg * 4]) = v;
            }
            __syncthreads();
            #pragma unroll
            for (int d = 0; d < DT; d++) {
                float4 a0 = *reinterpret_cast<const float4*>(&xs[d * PT + ty * 8]);
                float4 a1 = *reinterpret_cast<const float4*>(&xs[d * PT + ty * 8 + 4]);
                ulonglong2 e0 = *reinterpret_cast<const ulonglong2*>(&es[d * ESTRIDE + tx * 8]);
                ulonglong2 e1 = *reinterpret_cast<const ulonglong2*>(&es[d * ESTRIDE + tx * 8 + 4]);
                unsigned long long ev[4] = {e0.x, e0.y, e1.x, e1.y};
                float xv[8] = {a0.x, a0.y, a0.z, a0.w, a1.x, a1.y, a1.z, a1.w};
                #pragma unroll
                for (int i = 0; i < 8; i++) {
                    unsigned long long xp = pack2(xv[i], xv[i]);
                    #pragma unroll
                    for (int j = 0; j < 4; j++) acc[i][j] = fma2(xp, ev[j], acc[i][j]);
                }
            }
        }
        // per-chunk argmin, then fold into running best (ks ascending -> strict <
        // keeps lowest index, matching jnp.argmin tie-breaking)
        #pragma unroll
        for (int i = 0; i < 8; i++) {
            float v = 3.4e38f; int vi = 0;
            #pragma unroll
            for (int j = 0; j < 4; j++) {
                float a, c;
                unpack2(acc[i][j], a, c);
                int k0 = kbase + 2 * j;
                if (a < v) { v = a; vi = k0; }
                if (c < v) { v = c; vi = k0 + 1; }
            }
            #pragma unroll
            for (int o = 8; o >= 1; o >>= 1) {
                float ov = __shfl_xor_sync(0xffffffffu, v, o);
                int   oi = __shfl_xor_sync(0xffffffffu, vi, o);
                if (ov < v || (ov == v && oi < vi)) { v = ov; vi = oi; }
            }
            if (v < best[i]) { best[i] = v; besti[i] = vi; }
        }
    }
    if (tx == 0) {
        int n0 = b * BHW + hw0 + ty * 8;
        #pragma unroll
        for (int i = 0; i < 8; i++) g_idx[n0 + i] = besti[i];
    }
}

// ---- kernel 3: gather quantized (in [B,C,H,W] layout) + commitment-loss partials ----
__global__ void quantize_kernel(const float* __restrict__ x,
                                const float* __restrict__ emb,
                                float* __restrict__ outq) {
    int o = blockIdx.x * 256 + threadIdx.x;      // 0..QELEMS-1
    int hw = o & (BHW - 1);
    int d  = (o >> 12) & (D - 1);
    int b  = o >> 20;
    int n  = (b << 12) | hw;
    int k  = g_idx[n];
    float q  = __ldg(emb + (size_t)k * D + d);
    float xv = x[o];
    outq[o] = q;
    float diff = q - xv;
    float l = diff * diff;
    #pragma unroll
    for (int off = 16; off; off >>= 1) l += __shfl_xor_sync(0xffffffffu, l, off);
    __shared__ float ls[8];
    int lane = threadIdx.x & 31, w = threadIdx.x >> 5;
    if (lane == 0) ls[w] = l;
    __syncthreads();
    if (threadIdx.x == 0) {
        float s = 0.f;
        #pragma unroll
        for (int i = 0; i < 8; i++) s += ls[i];
        atomicAdd(&g_loss, s);
    }
}

// ---- kernel 4: histogram of codes ----
__global__ void hist_kernel() {
    int n = blockIdx.x * 256 + threadIdx.x;
    atomicAdd(&g_counts[g_idx[n]], 1);
}

// ---- kernel 5: one-hot encodings (float2 stores: base only 8B-aligned) ----
__global__ void enc_kernel(float2* __restrict__ enc) {
    int i2 = blockIdx.x * 256 + threadIdx.x;   // 0..(NPIX*K/2 - 1)
    int n = i2 >> 10;          // K/2 = 1024 float2 per row
    int j = (i2 & 1023) << 1;
    int k = g_idx[n];
    float2 v;
    v.x = (j == k)     ? 1.f : 0.f;
    v.y = (j + 1 == k) ? 1.f : 0.f;
    enc[i2] = v;
}

// ---- kernel 6: loss + perplexity scalars ----
__global__ void final_kernel(float* __restrict__ out) {
    __shared__ float sh[256];
    int t = threadIdx.x;
    float s = 0.f;
    for (int k = t; k < K; k += 256) {
        float p = (float)g_counts[k] * (1.0f / (float)NPIX);
        s += p * logf(p + 1e-10f);
    }
    sh[t] = s;
    __syncthreads();
    for (int o = 128; o; o >>= 1) {
        if (t < o) sh[t] += sh[t + o];
        __syncthreads();
    }
    if (t == 0) {
        out[0] = 0.25f * g_loss / (float)QELEMS;   // COMMITMENT_COST * mean
        out[1 + QELEMS] = expf(-sh[0]);            // perplexity
    }
}

extern "C" void kernel_launch(void* const* d_in, const int* in_sizes, int n_in,
                              void* d_out, int out_size) {
    const float* x   = (const float*)d_in[0];   // [16,256,64,64]
    const float* emb = (const float*)d_in[1];   // [2048,256]
    float* out  = (float*)d_out;
    float* outq = out + 1;                       // quantized_st
    float2* enc = (float2*)(out + 2 + QELEMS);   // encodings (8B aligned)

    prep_kernel<<<8, 256>>>(emb);
    argmin_kernel<<<512, 256>>>(x, emb);
    quantize_kernel<<<QELEMS / 256, 256>>>(x, emb, outq);
    hist_kernel<<<NPIX / 256, 256>>>();
    enc_kernel<<<(NPIX * (K / 2)) / 256, 256>>>(enc);
    final_kernel<<<1, 256>>>(out);
}

// round 5
// speedup vs baseline: 1.1212x; 1.1212x over previous
#include <cuda_runtime.h>
#include <cstdint>

#define D     256
#define K     2048
#define BHW   4096
#define NPIX  65536
#define QELEMS 16777216

// ---------------- device scratch ----------------
__device__ float g_halfnorm[K];
__device__ int   g_idx[NPIX];
__device__ int   g_counts[K];
__device__ float g_loss;

// ---------------- helpers ----------------
__device__ __forceinline__ float tf32_rna(float v) {
    uint32_t h;
    asm("cvt.rna.tf32.f32 %0, %1;" : "=r"(h) : "f"(v));
    return __uint_as_float(h);
}
__device__ __forceinline__ void mma8(float* c, const uint32_t* a, const uint32_t* b) {
    asm volatile("mma.sync.aligned.m16n8k8.row.col.f32.tf32.tf32.f32 "
        "{%0,%1,%2,%3}, {%4,%5,%6,%7}, {%8,%9}, {%0,%1,%2,%3};"
        : "+f"(c[0]), "+f"(c[1]), "+f"(c[2]), "+f"(c[3])
        : "r"(a[0]), "r"(a[1]), "r"(a[2]), "r"(a[3]), "r"(b[0]), "r"(b[1]));
}

// smem float offsets
#define SA_HI 0
#define SA_LO 4352        // 32*136
#define SB_HI 8704
#define SB_LO 13312       // + 128*36
#define SRED_V 17920
#define SRED_I 18432
#define SMEM_FLOATS 18944 // 75776 bytes

// ---------------- kernel 1: halfnorm + zero counters ----------------
__global__ void prep_kernel(const float* __restrict__ emb) {
    int k = blockIdx.x * blockDim.x + threadIdx.x;
    if (k < K) {
        const float4* row = reinterpret_cast<const float4*>(emb + (size_t)k * D);
        float s = 0.f;
        #pragma unroll
        for (int i = 0; i < D / 4; i++) {
            float4 v = row[i];
            s += v.x * v.x + v.y * v.y + v.z * v.z + v.w * v.w;
        }
        g_halfnorm[k] = 0.5f * s;
        g_counts[k] = 0;
        if (k == 0) g_loss = 0.f;
    }
}

// ---------------- kernel 2: tf32x3 mma.sync GEMM + argmin ----------------
// score(n,k) = 0.5||e_k||^2 - x_n . e_k
__global__ __launch_bounds__(256, 2) void argmin_mma_kernel(
    const float* __restrict__ x, const float* __restrict__ emb) {
    extern __shared__ float sm[];
    float* sAhi = sm + SA_HI;
    float* sAlo = sm + SA_LO;
    float* sBhi = sm + SB_HI;
    float* sBlo = sm + SB_LO;
    float* srv  = sm + SRED_V;
    int*   sri  = (int*)(sm + SRED_I);

    int tid = threadIdx.x;
    int w = tid >> 5, lane = tid & 31;
    int warpM = w >> 2, warpN = w & 3;
    int g = lane >> 2, tig = lane & 3;
    int blk = blockIdx.x;
    int b = blk >> 5, hw0 = (blk & 31) << 7;

    srv[tid] = 3.4e38f; srv[tid + 256] = 3.4e38f;
    sri[tid] = 0;       sri[tid + 256] = 0;
    __syncthreads();

    const float* xg = x + (size_t)b * (D * BHW) + hw0;   // [d][px], row stride 4096

    float acc[4][4][4];

    for (int nt = 0; nt < 16; nt++) {
        #pragma unroll
        for (int mf = 0; mf < 4; mf++)
            #pragma unroll
            for (int nf = 0; nf < 4; nf++)
                #pragma unroll
                for (int i = 0; i < 4; i++) acc[mf][nf][i] = 0.f;

        const float* eg = emb + (size_t)(nt * 128) * D;

        for (int s = 0; s < 8; s++) {
            int dt = s * 32;
            __syncthreads();
            // A: x slice [32 d][128 px], negate + tf32 split
            #pragma unroll
            for (int i = 0; i < 16; i++) {
                int e = tid + i * 256;
                int d = e >> 7, px = e & 127;
                float v = xg[(size_t)(dt + d) * BHW + px];
                float nv = -v;
                float hi = tf32_rna(nv);
                sAhi[d * 136 + px] = hi;
                sAlo[d * 136 + px] = tf32_rna(nv - hi);
            }
            // B: codebook slice [128 n][32 d], tf32 split
            #pragma unroll
            for (int i = 0; i < 16; i++) {
                int e = tid + i * 256;
                int n = e >> 5, dd = e & 31;
                float v = eg[(size_t)n * D + dt + dd];
                float hi = tf32_rna(v);
                sBhi[n * 36 + dd] = hi;
                sBlo[n * 36 + dd] = tf32_rna(v - hi);
            }
            __syncthreads();

            int pxb = warpM * 64;
            int nb  = warpN * 32;
            #pragma unroll
            for (int k8 = 0; k8 < 4; k8++) {
                int dr = k8 * 8 + tig;
                uint32_t bh[4][2], bl[4][2];
                #pragma unroll
                for (int nf = 0; nf < 4; nf++) {
                    int na = (nb + nf * 8 + g) * 36 + dr;
                    bh[nf][0] = __float_as_uint(sBhi[na]);
                    bh[nf][1] = __float_as_uint(sBhi[na + 4]);
                    bl[nf][0] = __float_as_uint(sBlo[na]);
                    bl[nf][1] = __float_as_uint(sBlo[na + 4]);
                }
                uint32_t af[4][4];
                #pragma unroll
                for (int mf = 0; mf < 4; mf++) {
                    int pa = pxb + mf * 16 + g;
                    af[mf][0] = __float_as_uint(sAhi[dr * 136 + pa]);
                    af[mf][1] = __float_as_uint(sAhi[dr * 136 + pa + 8]);
                    af[mf][2] = __float_as_uint(sAhi[(dr + 4) * 136 + pa]);
                    af[mf][3] = __float_as_uint(sAhi[(dr + 4) * 136 + pa + 8]);
                }
                #pragma unroll
                for (int mf = 0; mf < 4; mf++)
                    #pragma unroll
                    for (int nf = 0; nf < 4; nf++) mma8(acc[mf][nf], af[mf], bh[nf]);
                #pragma unroll
                for (int mf = 0; mf < 4; mf++)
                    #pragma unroll
                    for (int nf = 0; nf < 4; nf++) mma8(acc[mf][nf], af[mf], bl[nf]);
                #pragma unroll
                for (int mf = 0; mf < 4; mf++) {
                    int pa = pxb + mf * 16 + g;
                    af[mf][0] = __float_as_uint(sAlo[dr * 136 + pa]);
                    af[mf][1] = __float_as_uint(sAlo[dr * 136 + pa + 8]);
                    af[mf][2] = __float_as_uint(sAlo[(dr + 4) * 136 + pa]);
                    af[mf][3] = __float_as_uint(sAlo[(dr + 4) * 136 + pa + 8]);
                }
                #pragma unroll
                for (int mf = 0; mf < 4; mf++)
                    #pragma unroll
                    for (int nf = 0; nf < 4; nf++) mma8(acc[mf][nf], af[mf], bh[nf]);
            }
        }
        // epilogue for this 128-code tile: add halfnorm, fold argmin into smem slots
        float hn[4][2];
        int colbase = nt * 128 + warpN * 32 + tig * 2;
        #pragma unroll
        for (int nf = 0; nf < 4; nf++) {
            hn[nf][0] = __ldg(&g_halfnorm[colbase + nf * 8]);
            hn[nf][1] = __ldg(&g_halfnorm[colbase + nf * 8 + 1]);
        }
        #pragma unroll
        for (int mf = 0; mf < 4; mf++) {
            #pragma unroll
            for (int half = 0; half < 2; half++) {
                float v = 3.4e38f; int vi = 0;
                #pragma unroll
                for (int nf = 0; nf < 4; nf++) {
                    #pragma unroll
                    for (int c = 0; c < 2; c++) {
                        float sc = acc[mf][nf][half * 2 + c] + hn[nf][c];
                        int ci = colbase + nf * 8 + c;
                        if (sc < v) { v = sc; vi = ci; }
                    }
                }
                #pragma unroll
                for (int o = 1; o <= 2; o <<= 1) {
                    float ov = __shfl_xor_sync(0xffffffffu, v, o);
                    int   oi = __shfl_xor_sync(0xffffffffu, vi, o);
                    if (ov < v || (ov == v && oi < vi)) { v = ov; vi = oi; }
                }
                if (tig == 0) {
                    int row = warpM * 64 + mf * 16 + half * 8 + g;
                    int slot = row * 4 + warpN;
                    if (v < srv[slot] || (v == srv[slot] && vi < sri[slot])) {
                        srv[slot] = v; sri[slot] = vi;
                    }
                }
            }
        }
    }
    __syncthreads();
    if (tid < 128) {
        float v = srv[tid * 4]; int vi = sri[tid * 4];
        #pragma unroll
        for (int ww = 1; ww < 4; ww++) {
            float ov = srv[tid * 4 + ww]; int oi = sri[tid * 4 + ww];
            if (ov < v || (ov == v && oi < vi)) { v = ov; vi = oi; }
        }
        g_idx[blk * 128 + tid] = vi;
    }
}

// ---------------- kernel 3: gather quantized + loss partials ----------------
__global__ void quantize_kernel(const float* __restrict__ x,
                                const float* __restrict__ emb,
                                float* __restrict__ outq) {
    int o = blockIdx.x * 256 + threadIdx.x;
    int hw = o & (BHW - 1);
    int d  = (o >> 12) & (D - 1);
    int b  = o >> 20;
    int n  = (b << 12) | hw;
    int k  = g_idx[n];
    float q  = __ldg(emb + (size_t)k * D + d);
    float xv = x[o];
    outq[o] = q;
    float diff = q - xv;
    float l = diff * diff;
    #pragma unroll
    for (int off = 16; off; off >>= 1) l += __shfl_xor_sync(0xffffffffu, l, off);
    __shared__ float ls[8];
    int lane = threadIdx.x & 31, w = threadIdx.x >> 5;
    if (lane == 0) ls[w] = l;
    __syncthreads();
    if (threadIdx.x == 0) {
        float ssum = 0.f;
        #pragma unroll
        for (int i = 0; i < 8; i++) ssum += ls[i];
        atomicAdd(&g_loss, ssum);
    }
}

// ---------------- kernel 4: histogram ----------------
__global__ void hist_kernel() {
    int n = blockIdx.x * 256 + threadIdx.x;
    atomicAdd(&g_counts[g_idx[n]], 1);
}

// ---------------- kernel 5: one-hot encodings ----------------
__global__ void enc_kernel(float2* __restrict__ enc) {
    int i2 = blockIdx.x * 256 + threadIdx.x;
    int n = i2 >> 10;
    int j = (i2 & 1023) << 1;
    int k = g_idx[n];
    float2 v;
    v.x = (j == k)     ? 1.f : 0.f;
    v.y = (j + 1 == k) ? 1.f : 0.f;
    enc[i2] = v;
}

// ---------------- kernel 6: scalars ----------------
__global__ void final_kernel(float* __restrict__ out) {
    __shared__ float sh[256];
    int t = threadIdx.x;
    float s = 0.f;
    for (int k = t; k < K; k += 256) {
        float p = (float)g_counts[k] * (1.0f / (float)NPIX);
        s += p * logf(p + 1e-10f);
    }
    sh[t] = s;
    __syncthreads();
    for (int o = 128; o; o >>= 1) {
        if (t < o) sh[t] += sh[t + o];
        __syncthreads();
    }
    if (t == 0) {
        out[0] = 0.25f * g_loss / (float)QELEMS;
        out[1 + QELEMS] = expf(-sh[0]);
    }
}

extern "C" void kernel_launch(void* const* d_in, const int* in_sizes, int n_in,
                              void* d_out, int out_size) {
    const float* x   = (const float*)d_in[0];
    const float* emb = (const float*)d_in[1];
    float* out  = (float*)d_out;
    float* outq = out + 1;
    float2* enc = (float2*)(out + 2 + QELEMS);

    cudaFuncSetAttribute(argmin_mma_kernel, cudaFuncAttributeMaxDynamicSharedMemorySize,
                         SMEM_FLOATS * 4);

    prep_kernel<<<8, 256>>>(emb);
    argmin_mma_kernel<<<512, 256, SMEM_FLOATS * 4>>>(x, emb);
    quantize_kernel<<<QELEMS / 256, 256>>>(x, emb, outq);
    hist_kernel<<<NPIX / 256, 256>>>();
    enc_kernel<<<(NPIX * (K / 2)) / 256, 256>>>(enc);
    final_kernel<<<1, 256>>>(out);
}

// round 6
// speedup vs baseline: 1.6842x; 1.5021x over previous
#include <cuda_runtime.h>
#include <cuda_fp16.h>
#include <cstdint>

#define D      256
#define K      2048
#define BHW    4096
#define NPIX   65536
#define QELEMS 16777216

// ---------------- device scratch ----------------
// packed half2(d, d+1) words, tile-ready layouts
__device__ uint32_t g_xh2[(size_t)2 * 16 * 128 * 4096]; // [half][b][dpair][px]
__device__ uint32_t g_eh2[(size_t)2 * 128 * 2048];      // [half][dpair][n]
__device__ float g_halfnorm[K];
__device__ int   g_idx[NPIX];
__device__ int   g_counts[K];
__device__ float g_loss;

__device__ __forceinline__ void mma16(float* c, const uint32_t* a, const uint32_t* b) {
    asm volatile("mma.sync.aligned.m16n8k16.row.col.f32.f16.f16.f32 "
        "{%0,%1,%2,%3}, {%4,%5,%6,%7}, {%8,%9}, {%0,%1,%2,%3};"
        : "+f"(c[0]), "+f"(c[1]), "+f"(c[2]), "+f"(c[3])
        : "r"(a[0]), "r"(a[1]), "r"(a[2]), "r"(a[3]), "r"(b[0]), "r"(b[1]));
}
__device__ __forceinline__ uint32_t packsplit(float a, float b, int lo) {
    __half ha = __float2half_rn(a);
    __half hb = __float2half_rn(b);
    if (lo) {
        ha = __float2half_rn(a - __half2float(ha));
        hb = __float2half_rn(b - __half2float(hb));
    }
    __half2 h2 = __halves2half2(ha, hb);
    return *reinterpret_cast<uint32_t*>(&h2);
}

// ---------------- kernel 0: halfnorm + zero counters ----------------
__global__ void prep_kernel(const float* __restrict__ emb) {
    int k = blockIdx.x * blockDim.x + threadIdx.x;
    if (k < K) {
        const float4* row = reinterpret_cast<const float4*>(emb + (size_t)k * D);
        float s = 0.f;
        #pragma unroll
        for (int i = 0; i < D / 4; i++) {
            float4 v = row[i];
            s += v.x * v.x + v.y * v.y + v.z * v.z + v.w * v.w;
        }
        g_halfnorm[k] = 0.5f * s;
        g_counts[k] = 0;
        if (k == 0) g_loss = 0.f;
    }
}

// ---------------- kernel 1: split -x into packed hi/lo half2 ----------------
// grid: 16 b * 128 dpair blocks, 256 threads
__global__ void split_x_kernel(const float* __restrict__ x) {
    int b = blockIdx.x >> 7, dp = blockIdx.x & 127;
    const float* r0 = x + ((size_t)(b * 256 + 2 * dp)) * 4096;
    const float* r1 = r0 + 4096;
    size_t obase = ((size_t)(b)*128 + dp) * 4096;
    #pragma unroll
    for (int i = 0; i < 4; i++) {
        int px = (threadIdx.x + i * 256) * 4;
        float4 a = *reinterpret_cast<const float4*>(r0 + px);
        float4 c = *reinterpret_cast<const float4*>(r1 + px);
        uint4 hi, lo;
        hi.x = packsplit(-a.x, -c.x, 0); lo.x = packsplit(-a.x, -c.x, 1);
        hi.y = packsplit(-a.y, -c.y, 0); lo.y = packsplit(-a.y, -c.y, 1);
        hi.z = packsplit(-a.z, -c.z, 0); lo.z = packsplit(-a.z, -c.z, 1);
        hi.w = packsplit(-a.w, -c.w, 0); lo.w = packsplit(-a.w, -c.w, 1);
        *reinterpret_cast<uint4*>(&g_xh2[obase + px]) = hi;
        *reinterpret_cast<uint4*>(&g_xh2[(size_t)2 * 16 * 128 * 2048 * 2 / 2 + obase + px]) = lo; // half stride
    }
}

// ---------------- kernel 2: split e (transposed to [dpair][n]) ----------------
// grid dim3(32, 16): 64 n x 16 d per block
__global__ void split_e_kernel(const float* __restrict__ emb) {
    int n0 = blockIdx.x * 64, d0 = blockIdx.y * 16;
    int n = threadIdx.x & 63, dg = threadIdx.x >> 6;
    int d = d0 + dg * 4;
    float4 v = *reinterpret_cast<const float4*>(emb + (size_t)(n0 + n) * D + d);
    int dp = d >> 1;
    const size_t HS = (size_t)128 * 2048;
    g_eh2[(size_t)dp * 2048 + n0 + n]           = packsplit(v.x, v.y, 0);
    g_eh2[(size_t)(dp + 1) * 2048 + n0 + n]     = packsplit(v.z, v.w, 0);
    g_eh2[HS + (size_t)dp * 2048 + n0 + n]      = packsplit(v.x, v.y, 1);
    g_eh2[HS + (size_t)(dp + 1) * 2048 + n0 + n] = packsplit(v.z, v.w, 1);
}

// ---------------- kernel 3: fp16x3 mma GEMM + argmin ----------------
// smem word map: A [2][128][136] = 34816 w; B [2buf][2][16][136] = 8704 w;
// srv 512 f; sri 512 i. total 44544 words = 178176 B
#define AW(h, dp, px) (((h) * 128 + (dp)) * 136 + (px))
#define BW(buf, h, dpi, n) (34816 + (buf) * 4352 + ((h) * 16 + (dpi)) * 136 + (n))
#define SRV 43520
#define SRI 44032
#define SMEM_BYTES 178176

__global__ __launch_bounds__(256, 1) void argmin_fp16_kernel() {
    extern __shared__ uint32_t smw[];
    float* srv = reinterpret_cast<float*>(smw + SRV);
    int*   sri = reinterpret_cast<int*>(smw + SRI);

    int tid = threadIdx.x;
    int w = tid >> 5, lane = tid & 31;
    int warpM = w >> 2, warpN = w & 3;
    int g = lane >> 2, tig = lane & 3;
    int b = blockIdx.x >> 5, px0 = (blockIdx.x & 31) << 7;

    srv[tid] = 3.4e38f; srv[tid + 256] = 3.4e38f;
    sri[tid] = 0;       sri[tid + 256] = 0;

    // resident A copy: 8192 chunks of 16B
    const size_t XHS = (size_t)16 * 128 * 4096;
    #pragma unroll
    for (int i = 0; i < 32; i++) {
        int id = tid + i * 256;
        int h = id >> 12, dp = (id >> 5) & 127, ch = id & 31;
        uint4 v = *reinterpret_cast<const uint4*>(
            &g_xh2[(size_t)h * XHS + ((size_t)b * 128 + dp) * 4096 + px0 + ch * 4]);
        *reinterpret_cast<uint4*>(&smw[AW(h, dp, ch * 4)]) = v;
    }

    // prologue: B for step 0 into buf 0
    const size_t EHS = (size_t)128 * 2048;
    #pragma unroll
    for (int i = 0; i < 4; i++) {
        int id = tid + i * 256;
        int h = id >> 9, dp = (id >> 5) & 15, ch = id & 31;
        uint4 v = *reinterpret_cast<const uint4*>(
            &g_eh2[(size_t)h * EHS + (size_t)dp * 2048 + ch * 4]);
        *reinterpret_cast<uint4*>(&smw[BW(0, h, dp, ch * 4)]) = v;
    }

    float acc[4][4][4];

    for (int nt = 0; nt < 16; nt++) {
        #pragma unroll
        for (int mf = 0; mf < 4; mf++)
            #pragma unroll
            for (int nf = 0; nf < 4; nf++)
                #pragma unroll
                for (int i = 0; i < 4; i++) acc[mf][nf][i] = 0.f;

        for (int s = 0; s < 8; s++) {
            int step = nt * 8 + s;
            int buf = step & 1;
            __syncthreads();
            // prefetch next slice into other buffer
            if (step < 127) {
                int ns = step + 1;
                int nnt = ns >> 3, nss = ns & 7;
                #pragma unroll
                for (int i = 0; i < 4; i++) {
                    int id = tid + i * 256;
                    int h = id >> 9, dp = (id >> 5) & 15, ch = id & 31;
                    uint4 v = *reinterpret_cast<const uint4*>(
                        &g_eh2[(size_t)h * EHS + (size_t)(nss * 16 + dp) * 2048 +
                               nnt * 128 + ch * 4]);
                    *reinterpret_cast<uint4*>(&smw[BW(buf ^ 1, h, dp, ch * 4)]) = v;
                }
            }
            // MMA on buf
            int nb = warpN * 32;
            #pragma unroll
            for (int k16h = 0; k16h < 2; k16h++) {
                int ra = s * 16 + k16h * 8 + tig;
                int dpi = k16h * 8 + tig;
                uint32_t bh[4][2], bl[4][2];
                #pragma unroll
                for (int nf = 0; nf < 4; nf++) {
                    int nn = nb + nf * 8 + g;
                    bh[nf][0] = smw[BW(buf, 0, dpi, nn)];
                    bh[nf][1] = smw[BW(buf, 0, dpi + 4, nn)];
                    bl[nf][0] = smw[BW(buf, 1, dpi, nn)];
                    bl[nf][1] = smw[BW(buf, 1, dpi + 4, nn)];
                }
                #pragma unroll
                for (int mf = 0; mf < 4; mf++) {
                    int pa = warpM * 64 + mf * 16 + g;
                    uint32_t ah[4], al[4];
                    ah[0] = smw[AW(0, ra, pa)];
                    ah[1] = smw[AW(0, ra, pa + 8)];
                    ah[2] = smw[AW(0, ra + 4, pa)];
                    ah[3] = smw[AW(0, ra + 4, pa + 8)];
                    al[0] = smw[AW(1, ra, pa)];
                    al[1] = smw[AW(1, ra, pa + 8)];
                    al[2] = smw[AW(1, ra + 4, pa)];
                    al[3] = smw[AW(1, ra + 4, pa + 8)];
                    #pragma unroll
                    for (int nf = 0; nf < 4; nf++) {
                        mma16(acc[mf][nf], ah, bh[nf]);
                        mma16(acc[mf][nf], ah, bl[nf]);
                        mma16(acc[mf][nf], al, bh[nf]);
                    }
                }
            }
        }
        // epilogue: add halfnorm, fold argmin
        float hn[4][2];
        int colbase = nt * 128 + warpN * 32 + tig * 2;
        #pragma unroll
        for (int nf = 0; nf < 4; nf++) {
            hn[nf][0] = __ldg(&g_halfnorm[colbase + nf * 8]);
            hn[nf][1] = __ldg(&g_halfnorm[colbase + nf * 8 + 1]);
        }
        #pragma unroll
        for (int mf = 0; mf < 4; mf++) {
            #pragma unroll
            for (int half = 0; half < 2; half++) {
                float v = 3.4e38f; int vi = 0;
                #pragma unroll
                for (int nf = 0; nf < 4; nf++) {
                    #pragma unroll
                    for (int c = 0; c < 2; c++) {
                        float sc = acc[mf][nf][half * 2 + c] + hn[nf][c];
                        int ci = colbase + nf * 8 + c;
                        if (sc < v) { v = sc; vi = ci; }
                    }
                }
                #pragma unroll
                for (int o = 1; o <= 2; o <<= 1) {
                    float ov = __shfl_xor_sync(0xffffffffu, v, o);
                    int   oi = __shfl_xor_sync(0xffffffffu, vi, o);
                    if (ov < v || (ov == v && oi < vi)) { v = ov; vi = oi; }
                }
                if (tig == 0) {
                    int row = warpM * 64 + mf * 16 + half * 8 + g;
                    int slot = row * 4 + warpN;
                    if (v < srv[slot] || (v == srv[slot] && vi < sri[slot])) {
                        srv[slot] = v; sri[slot] = vi;
                    }
                }
            }
        }
    }
    __syncthreads();
    if (tid < 128) {
        float v = srv[tid * 4]; int vi = sri[tid * 4];
        #pragma unroll
        for (int ww = 1; ww < 4; ww++) {
            float ov = srv[tid * 4 + ww]; int oi = sri[tid * 4 + ww];
            if (ov < v || (ov == v && oi < vi)) { v = ov; vi = oi; }
        }
        g_idx[blockIdx.x * 128 + tid] = vi;
    }
}

// ---------------- kernel 4: gather quantized + loss partials ----------------
__global__ void quantize_kernel(const float* __restrict__ x,
                                const float* __restrict__ emb,
                                float* __restrict__ outq) {
    int o = blockIdx.x * 256 + threadIdx.x;
    int hw = o & (BHW - 1);
    int d  = (o >> 12) & (D - 1);
    int b  = o >> 20;
    int n  = (b << 12) | hw;
    int k  = g_idx[n];
    float q  = __ldg(emb + (size_t)k * D + d);
    float xv = x[o];
    outq[o] = q;
    float diff = q - xv;
    float l = diff * diff;
    #pragma unroll
    for (int off = 16; off; off >>= 1) l += __shfl_xor_sync(0xffffffffu, l, off);
    __shared__ float ls[8];
    int lane = threadIdx.x & 31, w = threadIdx.x >> 5;
    if (lane == 0) ls[w] = l;
    __syncthreads();
    if (threadIdx.x == 0) {
        float ssum = 0.f;
        #pragma unroll
        for (int i = 0; i < 8; i++) ssum += ls[i];
        atomicAdd(&g_loss, ssum);
    }
}

// ---------------- kernel 5: histogram ----------------
__global__ void hist_kernel() {
    int n = blockIdx.x * 256 + threadIdx.x;
    atomicAdd(&g_counts[g_idx[n]], 1);
}

// ---------------- kernel 6: one-hot encodings ----------------
__global__ void enc_kernel(float2* __restrict__ enc) {
    int i2 = blockIdx.x * 256 + threadIdx.x;
    int n = i2 >> 10;
    int j = (i2 & 1023) << 1;
    int k = g_idx[n];
    float2 v;
    v.x = (j == k)     ? 1.f : 0.f;
    v.y = (j + 1 == k) ? 1.f : 0.f;
    enc[i2] = v;
}

// ---------------- kernel 7: scalars ----------------
__global__ void final_kernel(float* __restrict__ out) {
    __shared__ float sh[256];
    int t = threadIdx.x;
    float s = 0.f;
    for (int k = t; k < K; k += 256) {
        float p = (float)g_counts[k] * (1.0f / (float)NPIX);
        s += p * logf(p + 1e-10f);
    }
    sh[t] = s;
    __syncthreads();
    for (int o = 128; o; o >>= 1) {
        if (t < o) sh[t] += sh[t + o];
        __syncthreads();
    }
    if (t == 0) {
        out[0] = 0.25f * g_loss / (float)QELEMS;
        out[1 + QELEMS] = expf(-sh[0]);
    }
}

extern "C" void kernel_launch(void* const* d_in, const int* in_sizes, int n_in,
                              void* d_out, int out_size) {
    const float* x   = (const float*)d_in[0];
    const float* emb = (const float*)d_in[1];
    float* out  = (float*)d_out;
    float* outq = out + 1;
    float2* enc = (float2*)(out + 2 + QELEMS);

    cudaFuncSetAttribute(argmin_fp16_kernel, cudaFuncAttributeMaxDynamicSharedMemorySize,
                         SMEM_BYTES);

    prep_kernel<<<8, 256>>>(emb);                         // launch 0
    split_x_kernel<<<16 * 128, 256>>>(x);                 // launch 1
    split_e_kernel<<<dim3(32, 16), 256>>>(emb);           // launch 2
    argmin_fp16_kernel<<<512, 256, SMEM_BYTES>>>();       // launch 3 (profiled slot)
    quantize_kernel<<<QELEMS / 256, 256>>>(x, emb, outq); // launch 4
    hist_kernel<<<NPIX / 256, 256>>>();                   // launch 5
    enc_kernel<<<(NPIX * (K / 2)) / 256, 256>>>(enc);     // launch 6
    final_kernel<<<1, 256>>>(out);                        // launch 7
}

// round 8
// speedup vs baseline: 1.8830x; 1.1181x over previous
#include <cuda_runtime.h>
#include <cuda_fp16.h>
#include <cstdint>

#define D      256
#define K      2048
#define BHW    4096
#define NPIX   65536
#define QELEMS 16777216

// ---------------- device scratch ----------------
__device__ uint32_t g_xh2[(size_t)2 * 16 * 128 * 4096]; // [half][b][dpair][px]
__device__ uint32_t g_eh2[(size_t)2 * 128 * 2048];      // [half][dpair][n]
__device__ float g_halfnorm[K];
__device__ int   g_idx[NPIX];
__device__ int   g_counts[K];
__device__ float g_loss;

__device__ __forceinline__ void mma16(float* c, const uint32_t* a, const uint32_t* b) {
    asm volatile("mma.sync.aligned.m16n8k16.row.col.f32.f16.f16.f32 "
        "{%0,%1,%2,%3}, {%4,%5,%6,%7}, {%8,%9}, {%0,%1,%2,%3};"
        : "+f"(c[0]), "+f"(c[1]), "+f"(c[2]), "+f"(c[3])
        : "r"(a[0]), "r"(a[1]), "r"(a[2]), "r"(a[3]), "r"(b[0]), "r"(b[1]));
}
__device__ __forceinline__ uint32_t packsplit(float a, float b, int lo) {
    __half ha = __float2half_rn(a);
    __half hb = __float2half_rn(b);
    if (lo) {
        ha = __float2half_rn(a - __half2float(ha));
        hb = __float2half_rn(b - __half2float(hb));
    }
    __half2 h2 = __halves2half2(ha, hb);
    return *reinterpret_cast<uint32_t*>(&h2);
}

// ---------------- kernel 0: halfnorm + zero counters ----------------
__global__ void prep_kernel(const float* __restrict__ emb) {
    int k = blockIdx.x * blockDim.x + threadIdx.x;
    if (k < K) {
        const float4* row = reinterpret_cast<const float4*>(emb + (size_t)k * D);
        float s = 0.f;
        #pragma unroll
        for (int i = 0; i < D / 4; i++) {
            float4 v = row[i];
            s += v.x * v.x + v.y * v.y + v.z * v.z + v.w * v.w;
        }
        g_halfnorm[k] = 0.5f * s;
        g_counts[k] = 0;
        if (k == 0) g_loss = 0.f;
    }
}

// ---------------- kernel 1: split -x into packed hi/lo half2 ----------------
__global__ void split_x_kernel(const float* __restrict__ x) {
    const size_t XHS = (size_t)16 * 128 * 4096;
    int b = blockIdx.x >> 7, dp = blockIdx.x & 127;
    const float* r0 = x + ((size_t)(b * 256 + 2 * dp)) * 4096;
    const float* r1 = r0 + 4096;
    size_t obase = ((size_t)(b)*128 + dp) * 4096;
    #pragma unroll
    for (int i = 0; i < 4; i++) {
        int px = (threadIdx.x + i * 256) * 4;
        float4 a = *reinterpret_cast<const float4*>(r0 + px);
        float4 c = *reinterpret_cast<const float4*>(r1 + px);
        uint4 hi, lo;
        hi.x = packsplit(-a.x, -c.x, 0); lo.x = packsplit(-a.x, -c.x, 1);
        hi.y = packsplit(-a.y, -c.y, 0); lo.y = packsplit(-a.y, -c.y, 1);
        hi.z = packsplit(-a.z, -c.z, 0); lo.z = packsplit(-a.z, -c.z, 1);
        hi.w = packsplit(-a.w, -c.w, 0); lo.w = packsplit(-a.w, -c.w, 1);
        *reinterpret_cast<uint4*>(&g_xh2[obase + px]) = hi;
        *reinterpret_cast<uint4*>(&g_xh2[XHS + obase + px]) = lo;
    }
}

// ---------------- kernel 2: split e (transposed to [dpair][n]) ----------------
__global__ void split_e_kernel(const float* __restrict__ emb) {
    int n0 = blockIdx.x * 64, d0 = blockIdx.y * 16;
    int n = threadIdx.x & 63, dg = threadIdx.x >> 6;
    int d = d0 + dg * 4;
    float4 v = *reinterpret_cast<const float4*>(emb + (size_t)(n0 + n) * D + d);
    int dp = d >> 1;
    const size_t HS = (size_t)128 * 2048;
    g_eh2[(size_t)dp * 2048 + n0 + n]            = packsplit(v.x, v.y, 0);
    g_eh2[(size_t)(dp + 1) * 2048 + n0 + n]      = packsplit(v.z, v.w, 0);
    g_eh2[HS + (size_t)dp * 2048 + n0 + n]       = packsplit(v.x, v.y, 1);
    g_eh2[HS + (size_t)(dp + 1) * 2048 + n0 + n] = packsplit(v.z, v.w, 1);
}

// ---------------- kernel 3: fp16x3 mma GEMM + argmin, 512 threads ----------------
// smem words: A [2][128][136]=34816 | B [2buf][2][32][136]=17408 | srv 512 | sri 512
#define AW(h, dp, px) (((h) * 128 + (dp)) * 136 + (px))
#define BW(buf, h, dpi, n) (34816 + (buf) * 8704 + ((h) * 32 + (dpi)) * 136 + (n))
#define SRV 52224
#define SRI 52736
#define SMEM_BYTES 212992

__global__ __launch_bounds__(512, 1) void argmin_fp16_kernel() {
    extern __shared__ uint32_t smw[];
    float* srv = reinterpret_cast<float*>(smw + SRV);
    int*   sri = reinterpret_cast<int*>(smw + SRI);

    int tid = threadIdx.x;
    int w = tid >> 5, lane = tid & 31;
    int warpM = w >> 2, warpN = w & 3;         // 4 x 4 warp grid, 32px x 32n tiles
    int g = lane >> 2, tig = lane & 3;
    int b = blockIdx.x >> 5, px0 = (blockIdx.x & 31) << 7;

    srv[tid] = 3.4e38f;
    sri[tid] = 0;

    // resident A copy: 8192 uint4
    const size_t XHS = (size_t)16 * 128 * 4096;
    #pragma unroll
    for (int i = 0; i < 16; i++) {
        int id = tid + i * 512;
        int row = id >> 5, px4 = id & 31;
        int h = row >> 7, dp = row & 127;
        uint4 v = *reinterpret_cast<const uint4*>(
            &g_xh2[(size_t)h * XHS + ((size_t)b * 128 + dp) * 4096 + px0 + px4 * 4]);
        *reinterpret_cast<uint4*>(&smw[AW(h, dp, px4 * 4)]) = v;
    }

    // prologue: B for step 0 (nt=0, d-slice 0) into buf 0
    const size_t EHS = (size_t)128 * 2048;
    #pragma unroll
    for (int i = 0; i < 4; i++) {
        int id = tid + i * 512;
        int row = id >> 5, n4 = id & 31;
        int h = row >> 5, dp = row & 31;
        uint4 v = *reinterpret_cast<const uint4*>(
            &g_eh2[(size_t)h * EHS + (size_t)dp * 2048 + n4 * 4]);
        *reinterpret_cast<uint4*>(&smw[BW(0, h, dp, n4 * 4)]) = v;
    }

    float acc[2][4][4];

    for (int nt = 0; nt < 16; nt++) {
        #pragma unroll
        for (int mf = 0; mf < 2; mf++)
            #pragma unroll
            for (int nf = 0; nf < 4; nf++)
                #pragma unroll
                for (int i = 0; i < 4; i++) acc[mf][nf][i] = 0.f;

        for (int s = 0; s < 4; s++) {          // 64-d slices
            int step = nt * 4 + s;
            int buf = step & 1;
            __syncthreads();
            if (step < 63) {
                int ns = step + 1;
                int nnt = ns >> 2, nss = ns & 3;
                #pragma unroll
                for (int i = 0; i < 4; i++) {
                    int id = tid + i * 512;
                    int row = id >> 5, n4 = id & 31;
                    int h = row >> 5, dp = row & 31;
                    uint4 v = *reinterpret_cast<const uint4*>(
                        &g_eh2[(size_t)h * EHS + (size_t)(nss * 32 + dp) * 2048 +
                               nnt * 128 + n4 * 4]);
                    *reinterpret_cast<uint4*>(&smw[BW(buf ^ 1, h, dp, n4 * 4)]) = v;
                }
            }
            #pragma unroll
            for (int kb = 0; kb < 4; kb++) {
                int ra = s * 32 + kb * 8 + tig;     // A dpair row
                int dpi = kb * 8 + tig;             // B dpair row (in-slice)
                uint32_t bh[4][2], bl[4][2];
                #pragma unroll
                for (int nf = 0; nf < 4; nf++) {
                    int nn = warpN * 32 + nf * 8 + g;
                    bh[nf][0] = smw[BW(buf, 0, dpi, nn)];
                    bh[nf][1] = smw[BW(buf, 0, dpi + 4, nn)];
                    bl[nf][0] = smw[BW(buf, 1, dpi, nn)];
                    bl[nf][1] = smw[BW(buf, 1, dpi + 4, nn)];
                }
                #pragma unroll
                for (int mf = 0; mf < 2; mf++) {
                    int pa = warpM * 32 + mf * 16 + g;
                    uint32_t ah[4], al[4];
                    ah[0] = smw[AW(0, ra, pa)];
                    ah[1] = smw[AW(0, ra, pa + 8)];
                    ah[2] = smw[AW(0, ra + 4, pa)];
                    ah[3] = smw[AW(0, ra + 4, pa + 8)];
                    al[0] = smw[AW(1, ra, pa)];
                    al[1] = smw[AW(1, ra, pa + 8)];
                    al[2] = smw[AW(1, ra + 4, pa)];
                    al[3] = smw[AW(1, ra + 4, pa + 8)];
                    #pragma unroll
                    for (int nf = 0; nf < 4; nf++) {
                        mma16(acc[mf][nf], ah, bh[nf]);
                        mma16(acc[mf][nf], ah, bl[nf]);
                        mma16(acc[mf][nf], al, bh[nf]);
                    }
                }
            }
        }
        // epilogue: add halfnorm, fold argmin into per-(row,warpN) slots
        float hn[4][2];
        int colbase = nt * 128 + warpN * 32 + tig * 2;
        #pragma unroll
        for (int nf = 0; nf < 4; nf++) {
            hn[nf][0] = __ldg(&g_halfnorm[colbase + nf * 8]);
            hn[nf][1] = __ldg(&g_halfnorm[colbase + nf * 8 + 1]);
        }
        #pragma unroll
        for (int mf = 0; mf < 2; mf++) {
            #pragma unroll
            for (int half = 0; half < 2; half++) {
                float v = 3.4e38f; int vi = 0;
                #pragma unroll
                for (int nf = 0; nf < 4; nf++) {
                    #pragma unroll
                    for (int c = 0; c < 2; c++) {
                        float sc = acc[mf][nf][half * 2 + c] + hn[nf][c];
                        int ci = colbase + nf * 8 + c;
                        if (sc < v) { v = sc; vi = ci; }
                    }
                }
                #pragma unroll
                for (int o = 1; o <= 2; o <<= 1) {
                    float ov = __shfl_xor_sync(0xffffffffu, v, o);
                    int   oi = __shfl_xor_sync(0xffffffffu, vi, o);
                    if (ov < v || (ov == v && oi < vi)) { v = ov; vi = oi; }
                }
                if (tig == 0) {
                    int row = warpM * 32 + mf * 16 + half * 8 + g;
                    int slot = row * 4 + warpN;
                    if (v < srv[slot] || (v == srv[slot] && vi < sri[slot])) {
                        srv[slot] = v; sri[slot] = vi;
                    }
                }
            }
        }
    }
    __syncthreads();
    if (tid < 128) {
        float v = srv[tid * 4]; int vi = sri[tid * 4];
        #pragma unroll
        for (int ww = 1; ww < 4; ww++) {
            float ov = srv[tid * 4 + ww]; int oi = sri[tid * 4 + ww];
            if (ov < v || (ov == v && oi < vi)) { v = ov; vi = oi; }
        }
        g_idx[blockIdx.x * 128 + tid] = vi;
    }
}

// ---------------- kernel 4: gather quantized + loss partials ----------------
__global__ void quantize_kernel(const float* __restrict__ x,
                                const float* __restrict__ emb,
                                float* __restrict__ outq) {
    int o = blockIdx.x * 256 + threadIdx.x;
    int hw = o & (BHW - 1);
    int d  = (o >> 12) & (D - 1);
    int b  = o >> 20;
    int n  = (b << 12) | hw;
    int k  = g_idx[n];
    float q  = __ldg(emb + (size_t)k * D + d);
    float xv = x[o];
    __stcs(outq + o, q);
    float diff = q - xv;
    float l = diff * diff;
    #pragma unroll
    for (int off = 16; off; off >>= 1) l += __shfl_xor_sync(0xffffffffu, l, off);
    __shared__ float ls[8];
    int lane = threadIdx.x & 31, w = threadIdx.x >> 5;
    if (lane == 0) ls[w] = l;
    __syncthreads();
    if (threadIdx.x == 0) {
        float ssum = 0.f;
        #pragma unroll
        for (int i = 0; i < 8; i++) ssum += ls[i];
        atomicAdd(&g_loss, ssum);
    }
}

// ---------------- kernel 5: histogram ----------------
__global__ void hist_kernel() {
    int n = blockIdx.x * 256 + threadIdx.x;
    atomicAdd(&g_counts[g_idx[n]], 1);
}

// ---------------- kernel 6: one-hot encodings ----------------
__global__ void enc_kernel(float2* __restrict__ enc) {
    int i2 = blockIdx.x * 256 + threadIdx.x;
    int n = i2 >> 10;
    int j = (i2 & 1023) << 1;
    int k = g_idx[n];
    float2 v;
    v.x = (j == k)     ? 1.f : 0.f;
    v.y = (j + 1 == k) ? 1.f : 0.f;
    __stcs(enc + i2, v);
}

// ---------------- kernel 7: scalars ----------------
__global__ void final_kernel(float* __restrict__ out) {
    __shared__ float sh[256];
    int t = threadIdx.x;
    float s = 0.f;
    for (int k = t; k < K; k += 256) {
        float p = (float)g_counts[k] * (1.0f / (float)NPIX);
        s += p * logf(p + 1e-10f);
    }
    sh[t] = s;
    __syncthreads();
    for (int o = 128; o; o >>= 1) {
        if (t < o) sh[t] += sh[t + o];
        __syncthreads();
    }
    if (t == 0) {
        out[0] = 0.25f * g_loss / (float)QELEMS;
        out[1 + QELEMS] = expf(-sh[0]);
    }
}

extern "C" void kernel_launch(void* const* d_in, const int* in_sizes, int n_in,
                              void* d_out, int out_size) {
    const float* x   = (const float*)d_in[0];
    const float* emb = (const float*)d_in[1];
    float* out  = (float*)d_out;
    float* outq = out + 1;
    float2* enc = (float2*)(out + 2 + QELEMS);

    cudaFuncSetAttribute(argmin_fp16_kernel, cudaFuncAttributeMaxDynamicSharedMemorySize,
                         SMEM_BYTES);

    prep_kernel<<<8, 256>>>(emb);                         // 0
    split_x_kernel<<<16 * 128, 256>>>(x);                 // 1
    split_e_kernel<<<dim3(32, 16), 256>>>(emb);           // 2
    argmin_fp16_kernel<<<512, 512, SMEM_BYTES>>>();       // 3 (profiled slot)
    quantize_kernel<<<QELEMS / 256, 256>>>(x, emb, outq); // 4
    hist_kernel<<<NPIX / 256, 256>>>();                   // 5
    enc_kernel<<<(NPIX * (K / 2)) / 256, 256>>>(enc);     // 6
    final_kernel<<<1, 256>>>(out);                        // 7
}

// round 9
// speedup vs baseline: 1.9815x; 1.0523x over previous
#include <cuda_runtime.h>
#include <cuda_fp16.h>
#include <cstdint>

#define D      256
#define K      2048
#define BHW    4096
#define NPIX   65536
#define QELEMS 16777216

// ---------------- device scratch ----------------
// A scratch: [b*32+pt][h][px 128][chunk 32 (^= px&7)] uint4 (chunk = 8 halves of d)
__device__ uint4 g_xA[(size_t)512 * 2 * 128 * 32];      // 64 MB
// B scratch: [nt*4+s][h][n 128][cl 8 (^= n&7)] uint4
__device__ uint4 g_xB[(size_t)64 * 2 * 128 * 8];        // 2 MB
__device__ float g_halfnorm[K];
__device__ int   g_idx[NPIX];
__device__ int   g_counts[K];
__device__ float g_loss;

__device__ __forceinline__ void mma16(float* c, const uint32_t* a, const uint32_t* b) {
    asm volatile("mma.sync.aligned.m16n8k16.row.col.f32.f16.f16.f32 "
        "{%0,%1,%2,%3}, {%4,%5,%6,%7}, {%8,%9}, {%0,%1,%2,%3};"
        : "+f"(c[0]), "+f"(c[1]), "+f"(c[2]), "+f"(c[3])
        : "r"(a[0]), "r"(a[1]), "r"(a[2]), "r"(a[3]), "r"(b[0]), "r"(b[1]));
}
__device__ __forceinline__ void ldsm4(uint32_t* r, uint32_t addr) {
    asm volatile("ldmatrix.sync.aligned.m8n8.x4.shared.b16 {%0,%1,%2,%3}, [%4];"
        : "=r"(r[0]), "=r"(r[1]), "=r"(r[2]), "=r"(r[3]) : "r"(addr));
}
__device__ __forceinline__ uint32_t smem_u32(const void* p) {
    uint32_t a;
    asm("{ .reg .u64 t; cvta.to.shared.u64 t, %1; cvt.u32.u64 %0, t; }" : "=r"(a) : "l"(p));
    return a;
}
#define CPASYNC(dst, src) \
    asm volatile("cp.async.ca.shared.global [%0], [%1], 16;" :: "r"(dst), "l"(src))
#define CPCOMMIT() asm volatile("cp.async.commit_group;" ::: "memory")
#define CPWAIT0()  asm volatile("cp.async.wait_group 0;" ::: "memory")

__device__ __forceinline__ uint32_t packh2(float a, float b) {
    __half2 h2 = __halves2half2(__float2half_rn(a), __float2half_rn(b));
    return *reinterpret_cast<uint32_t*>(&h2);
}

// ---------------- kernel 0: halfnorm + zero counters ----------------
__global__ void prep_kernel(const float* __restrict__ emb) {
    int k = blockIdx.x * blockDim.x + threadIdx.x;
    if (k < K) {
        const float4* row = reinterpret_cast<const float4*>(emb + (size_t)k * D);
        float s = 0.f;
        #pragma unroll
        for (int i = 0; i < D / 4; i++) {
            float4 v = row[i];
            s += v.x * v.x + v.y * v.y + v.z * v.z + v.w * v.w;
        }
        g_halfnorm[k] = 0.5f * s;
        g_counts[k] = 0;
        if (k == 0) g_loss = 0.f;
    }
}

// ---------------- kernel 1: split -x -> ldmatrix-ready A scratch ----------------
// grid: (b 16) x (pt 32) x (hpx 2); 256 threads; 64KB stage
__global__ void split_x_kernel(const float* __restrict__ x) {
    extern __shared__ uint4 stg[];   // [h 2][pxl 64][c 32]
    int blk = blockIdx.x;
    int b = blk >> 6, pt = (blk >> 1) & 31, hpx = blk & 1;
    int tid = threadIdx.x;
    int hw0 = pt * 128 + hpx * 64;

    #pragma unroll
    for (int it = 0; it < 8; it++) {
        int id = tid + it * 256;
        int pxl = id & 63, c = id >> 6;
        int px = hpx * 64 + pxl;
        float v[8];
        #pragma unroll
        for (int j = 0; j < 8; j++)
            v[j] = -x[((size_t)(b * 256 + c * 8 + j)) * 4096 + hw0 + pxl];
        __half hh[8];
        uint4 hi, lo;
        #pragma unroll
        for (int j = 0; j < 8; j++) hh[j] = __float2half_rn(v[j]);
        hi.x = packh2(v[0], v[1]); hi.y = packh2(v[2], v[3]);
        hi.z = packh2(v[4], v[5]); hi.w = packh2(v[6], v[7]);
        float r[8];
        #pragma unroll
        for (int j = 0; j < 8; j++) r[j] = v[j] - __half2float(hh[j]);
        lo.x = packh2(r[0], r[1]); lo.y = packh2(r[2], r[3]);
        lo.z = packh2(r[4], r[5]); lo.w = packh2(r[6], r[7]);
        int cs = c ^ (px & 7);
        stg[(0 * 64 + pxl) * 32 + cs] = hi;
        stg[(1 * 64 + pxl) * 32 + cs] = lo;
    }
    __syncthreads();
    size_t ob = (size_t)blk >> 1 << 13;  // (b*32+pt)*8192
    #pragma unroll
    for (int it = 0; it < 16; it++) {
        int id = tid + it * 256;         // [h][pxl][c']
        int h = id >> 11, pxl = (id >> 5) & 63, cp = id & 31;
        g_xA[ob + ((size_t)h * 128 + hpx * 64 + pxl) * 32 + cp] =
            stg[(h * 64 + pxl) * 32 + cp];
    }
}

// ---------------- kernel 2: split e -> ldmatrix-ready B scratch ----------------
// grid: 32 blocks (64 n each); 256 threads; 64KB stage
__global__ void split_e_kernel(const float* __restrict__ emb) {
    extern __shared__ uint4 stg[];   // [h 2][nl 64][c 32]
    int n0 = blockIdx.x * 64;
    int tid = threadIdx.x;
    #pragma unroll
    for (int it = 0; it < 8; it++) {
        int id = tid + it * 256;
        int c = id & 31, nl = id >> 5;
        float v[8];
        #pragma unroll
        for (int j = 0; j < 8; j++)
            v[j] = emb[(size_t)(n0 + nl) * D + c * 8 + j];
        __half hh[8];
        uint4 hi, lo;
        #pragma unroll
        for (int j = 0; j < 8; j++) hh[j] = __float2half_rn(v[j]);
        hi.x = packh2(v[0], v[1]); hi.y = packh2(v[2], v[3]);
        hi.z = packh2(v[4], v[5]); hi.w = packh2(v[6], v[7]);
        float r[8];
        #pragma unroll
        for (int j = 0; j < 8; j++) r[j] = v[j] - __half2float(hh[j]);
        lo.x = packh2(r[0], r[1]); lo.y = packh2(r[2], r[3]);
        lo.z = packh2(r[4], r[5]); lo.w = packh2(r[6], r[7]);
        int s = c >> 3, cl = c & 7;
        int cs = s * 8 + (cl ^ (nl & 7));
        stg[(0 * 64 + nl) * 32 + cs] = hi;
        stg[(1 * 64 + nl) * 32 + cs] = lo;
    }
    __syncthreads();
    int nt = n0 >> 7, nhalf = (n0 >> 6) & 1;
    #pragma unroll
    for (int it = 0; it < 16; it++) {
        int id = tid + it * 256;        // [s 4][h 2][nl 64][clp 8]
        int clp = id & 7, nl = (id >> 3) & 63, h = (id >> 9) & 1, s = id >> 10;
        g_xB[((((size_t)(nt * 4 + s) * 2 + h) * 128) + nhalf * 64 + nl) * 8 + clp] =
            stg[(h * 64 + nl) * 32 + s * 8 + clp];
    }
}

// ---------------- kernel 3: fp16x3 ldmatrix/cp.async GEMM + argmin ----------------
// smem uint4: A[2][128][32] = 8192 | B[2buf][2][128][8] = 4096 | srv/sri 4KB
#define ABYTES 131072
#define BBYTES 65536
#define SRVW   49152
#define SRIW   49664
#define SMEM_BYTES 200704

__global__ __launch_bounds__(512, 1) void argmin_fp16_kernel() {
    extern __shared__ uint4 sm4[];
    uint32_t sb = smem_u32(sm4);
    uint32_t* smw = reinterpret_cast<uint32_t*>(sm4);
    float* srv = reinterpret_cast<float*>(smw + SRVW);
    int*   sri = reinterpret_cast<int*>(smw + SRIW);

    int tid = threadIdx.x;
    int w = tid >> 5, lane = tid & 31;
    int warpM = w >> 2, warpN = w & 3;
    int g = lane >> 2, tig = lane & 3;

    srv[tid] = 3.4e38f;
    sri[tid] = 0;

    // prologue: A resident (16/thread) + B step0 (4/thread) via cp.async
    {
        const uint4* asrc = &g_xA[(size_t)blockIdx.x << 13];
        #pragma unroll
        for (int i = 0; i < 16; i++) {
            int id = tid + i * 512;
            CPASYNC(sb + id * 16, asrc + id);
        }
        #pragma unroll
        for (int i = 0; i < 4; i++) {
            int id = tid + i * 512;
            CPASYNC(sb + ABYTES + id * 16, &g_xB[id]);
        }
        CPCOMMIT();
        CPWAIT0();
    }

    // per-lane ldmatrix address components
    int pxA0 = warpM * 32 + (lane & 15);             // mf adds 16
    int kcA  = lane >> 4;                            // chunk low bit
    int nB0  = warpN * 32 + (lane & 7) + ((lane >> 4) << 3);  // p adds 16
    int kcB  = (lane >> 3) & 1;

    float acc[2][4][4];

    for (int nt = 0; nt < 16; nt++) {
        #pragma unroll
        for (int mf = 0; mf < 2; mf++)
            #pragma unroll
            for (int nf = 0; nf < 4; nf++)
                #pragma unroll
                for (int i = 0; i < 4; i++) acc[mf][nf][i] = 0.f;

        for (int s = 0; s < 4; s++) {
            int step = nt * 4 + s;
            int buf = step & 1;
            __syncthreads();
            if (step < 63) {
                const uint4* bsrc = &g_xB[(size_t)(step + 1) << 11];
                uint32_t bdst = sb + ABYTES + (buf ^ 1) * (BBYTES / 2);
                #pragma unroll
                for (int i = 0; i < 4; i++) {
                    int id = tid + i * 512;
                    CPASYNC(bdst + id * 16, bsrc + id);
                }
                CPCOMMIT();
            }
            uint32_t bbase = sb + ABYTES + buf * (BBYTES / 2);
            #pragma unroll
            for (int kb = 0; kb < 4; kb++) {
                int cA = s * 8 + kb * 2 + kcA;
                uint32_t ah[2][4], al[2][4];
                #pragma unroll
                for (int mf = 0; mf < 2; mf++) {
                    int px = pxA0 + mf * 16;
                    uint32_t ro = (uint32_t)(px * 32 + (cA ^ (px & 7))) * 16;
                    ldsm4(ah[mf], sb + ro);
                    ldsm4(al[mf], sb + 65536 + ro);   // h=1 plane: 128*32*16
                }
                int clB = kb * 2 + kcB;
                uint32_t bh[2][4], bl[2][4];
                #pragma unroll
                for (int p = 0; p < 2; p++) {
                    int n = nB0 + p * 16;
                    uint32_t ro = (uint32_t)(n * 8 + (clB ^ (n & 7))) * 16;
                    ldsm4(bh[p], bbase + ro);
                    ldsm4(bl[p], bbase + 16384 + ro); // h=1 plane: 128*8*16
                }
                #pragma unroll
                for (int mf = 0; mf < 2; mf++)
                    #pragma unroll
                    for (int nf = 0; nf < 4; nf++)
                        mma16(acc[mf][nf], ah[mf], &bh[nf >> 1][(nf & 1) * 2]);
                #pragma unroll
                for (int mf = 0; mf < 2; mf++)
                    #pragma unroll
                    for (int nf = 0; nf < 4; nf++)
                        mma16(acc[mf][nf], ah[mf], &bl[nf >> 1][(nf & 1) * 2]);
                #pragma unroll
                for (int mf = 0; mf < 2; mf++)
                    #pragma unroll
                    for (int nf = 0; nf < 4; nf++)
                        mma16(acc[mf][nf], al[mf], &bh[nf >> 1][(nf & 1) * 2]);
            }
            CPWAIT0();
        }
        // epilogue: add halfnorm, fold argmin
        float hn[4][2];
        int colbase = nt * 128 + warpN * 32 + tig * 2;
        #pragma unroll
        for (int nf = 0; nf < 4; nf++) {
            hn[nf][0] = __ldg(&g_halfnorm[colbase + nf * 8]);
            hn[nf][1] = __ldg(&g_halfnorm[colbase + nf * 8 + 1]);
        }
        #pragma unroll
        for (int mf = 0; mf < 2; mf++) {
            #pragma unroll
            for (int half = 0; half < 2; half++) {
                float v = 3.4e38f; int vi = 0;
                #pragma unroll
                for (int nf = 0; nf < 4; nf++) {
                    #pragma unroll
                    for (int c = 0; c < 2; c++) {
                        float sc = acc[mf][nf][half * 2 + c] + hn[nf][c];
                        int ci = colbase + nf * 8 + c;
                        if (sc < v) { v = sc; vi = ci; }
                    }
                }
                #pragma unroll
                for (int o = 1; o <= 2; o <<= 1) {
                    float ov = __shfl_xor_sync(0xffffffffu, v, o);
                    int   oi = __shfl_xor_sync(0xffffffffu, vi, o);
                    if (ov < v || (ov == v && oi < vi)) { v = ov; vi = oi; }
                }
                if (tig == 0) {
                    int row = warpM * 32 + mf * 16 + half * 8 + g;
                    int slot = row * 4 + warpN;
                    if (v < srv[slot] || (v == srv[slot] && vi < sri[slot])) {
                        srv[slot] = v; sri[slot] = vi;
                    }
                }
            }
        }
    }
    __syncthreads();
    if (tid < 128) {
        float v = srv[tid * 4]; int vi = sri[tid * 4];
        #pragma unroll
        for (int ww = 1; ww < 4; ww++) {
            float ov = srv[tid * 4 + ww]; int oi = sri[tid * 4 + ww];
            if (ov < v || (ov == v && oi < vi)) { v = ov; vi = oi; }
        }
        g_idx[blockIdx.x * 128 + tid] = vi;
    }
}

// ---------------- kernel 4: gather quantized + loss partials ----------------
__global__ void quantize_kernel(const float* __restrict__ x,
                                const float* __restrict__ emb,
                                float* __restrict__ outq) {
    int o = blockIdx.x * 256 + threadIdx.x;
    int hw = o & (BHW - 1);
    int d  = (o >> 12) & (D - 1);
    int b  = o >> 20;
    int n  = (b << 12) | hw;
    int k  = g_idx[n];
    float q  = __ldg(emb + (size_t)k * D + d);
    float xv = x[o];
    __stcs(outq + o, q);
    float diff = q - xv;
    float l = diff * diff;
    #pragma unroll
    for (int off = 16; off; off >>= 1) l += __shfl_xor_sync(0xffffffffu, l, off);
    __shared__ float ls[8];
    int lane = threadIdx.x & 31, w = threadIdx.x >> 5;
    if (lane == 0) ls[w] = l;
    __syncthreads();
    if (threadIdx.x == 0) {
        float ssum = 0.f;
        #pragma unroll
        for (int i = 0; i < 8; i++) ssum += ls[i];
        atomicAdd(&g_loss, ssum);
    }
}

// ---------------- kernel 5: histogram ----------------
__global__ void hist_kernel() {
    int n = blockIdx.x * 256 + threadIdx.x;
    atomicAdd(&g_counts[g_idx[n]], 1);
}

// ---------------- kernel 6: one-hot encodings ----------------
__global__ void enc_kernel(float2* __restrict__ enc) {
    int i2 = blockIdx.x * 256 + threadIdx.x;
    int n = i2 >> 10;
    int j = (i2 & 1023) << 1;
    int k = g_idx[n];
    float2 v;
    v.x = (j == k)     ? 1.f : 0.f;
    v.y = (j + 1 == k) ? 1.f : 0.f;
    __stcs(enc + i2, v);
}

// ---------------- kernel 7: scalars ----------------
__global__ void final_kernel(float* __restrict__ out) {
    __shared__ float sh[256];
    int t = threadIdx.x;
    float s = 0.f;
    for (int k = t; k < K; k += 256) {
        float p = (float)g_counts[k] * (1.0f / (float)NPIX);
        s += p * logf(p + 1e-10f);
    }
    sh[t] = s;
    __syncthreads();
    for (int o = 128; o; o >>= 1) {
        if (t < o) sh[t] += sh[t + o];
        __syncthreads();
    }
    if (t == 0) {
        out[0] = 0.25f * g_loss / (float)QELEMS;
        out[1 + QELEMS] = expf(-sh[0]);
    }
}

extern "C" void kernel_launch(void* const* d_in, const int* in_sizes, int n_in,
                              void* d_out, int out_size) {
    const float* x   = (const float*)d_in[0];
    const float* emb = (const float*)d_in[1];
    float* out  = (float*)d_out;
    float* outq = out + 1;
    float2* enc = (float2*)(out + 2 + QELEMS);

    cudaFuncSetAttribute(argmin_fp16_kernel, cudaFuncAttributeMaxDynamicSharedMemorySize,
                         SMEM_BYTES);
    cudaFuncSetAttribute(split_x_kernel, cudaFuncAttributeMaxDynamicSharedMemorySize,
                         65536);
    cudaFuncSetAttribute(split_e_kernel, cudaFuncAttributeMaxDynamicSharedMemorySize,
                         65536);

    prep_kernel<<<8, 256>>>(emb);                           // 0
    split_x_kernel<<<1024, 256, 65536>>>(x);                // 1
    split_e_kernel<<<32, 256, 65536>>>(emb);                // 2
    argmin_fp16_kernel<<<512, 512, SMEM_BYTES>>>();         // 3 (profiled slot)
    quantize_kernel<<<QELEMS / 256, 256>>>(x, emb, outq);   // 4
    hist_kernel<<<NPIX / 256, 256>>>();                     // 5
    enc_kernel<<<(NPIX * (K / 2)) / 256, 256>>>(enc);       // 6
    final_kernel<<<1, 256>>>(out);                          // 7
}